// round 6
// baseline (speedup 1.0000x reference)
#include <cuda_runtime.h>
#include <cuda_bf16.h>
#include <cstdint>

typedef unsigned long long ull;

// Problem constants
constexpr int NN = 100000;
constexpr int EE = 1250000;
constexpr int KTOT = 576;                 // 64 (root) + 8*64
constexpr int NK = NN * 8;                // (node, rel) keys
constexpr int NBLK2 = (NK + 1023) / 1024; // 782 scan blocks
constexpr int NCH = 9;                    // 1 root chunk + 8 relation chunks
constexpr int AS = 72;                    // bf16 A/B smem row stride (144 B)
constexpr int AFS = 68;                   // fp32 accumulation tile row stride

// ---------------- scratch ---------------------------------------------------
__device__ int g_cnt[NK];
__device__ int g_rowptr[NK];
__device__ int g_cursor[NK];
__device__ int g_epack[EE];    // src ids sorted by (dst, rel)
__device__ int g_bsum[NBLK2];
__device__ int g_bpre[NBLK2];
__device__ float g_H[(size_t)NN * 64];
__device__ __nv_bfloat16 g_Wt1h[64 * KTOT];
__device__ __nv_bfloat16 g_Wt1l[64 * KTOT];
__device__ __nv_bfloat16 g_Wt2h[32 * KTOT];
__device__ __nv_bfloat16 g_Wt2l[32 * KTOT];

// ---------------- helpers ---------------------------------------------------
__device__ __forceinline__ uint32_t smem_u32(const void* p) {
    uint32_t a;
    asm("{ .reg .u64 t; cvta.to.shared.u64 t, %1; cvt.u32.u64 %0, t; }" : "=r"(a) : "l"(p));
    return a;
}
__device__ __forceinline__ void sts128(uint32_t a, uint32_t x, uint32_t y, uint32_t z, uint32_t w) {
    asm volatile("st.shared.v4.b32 [%0], {%1,%2,%3,%4};" :: "r"(a), "r"(x), "r"(y), "r"(z), "r"(w) : "memory");
}
__device__ __forceinline__ uint32_t lds32(uint32_t a) {
    uint32_t v;
    asm volatile("ld.shared.b32 %0, [%1];" : "=r"(v) : "r"(a));
    return v;
}
__device__ __forceinline__ float2 lds64f(uint32_t a) {
    float2 v;
    asm volatile("ld.shared.v2.f32 {%0,%1}, [%2];" : "=f"(v.x), "=f"(v.y) : "r"(a));
    return v;
}
__device__ __forceinline__ void sts64f(uint32_t a, float2 v) {
    asm volatile("st.shared.v2.f32 [%0], {%1,%2};" :: "r"(a), "f"(v.x), "f"(v.y) : "memory");
}
__device__ __forceinline__ float4 lds128f(uint32_t a) {
    float4 v;
    asm volatile("ld.shared.v4.f32 {%0,%1,%2,%3}, [%4];"
                 : "=f"(v.x), "=f"(v.y), "=f"(v.z), "=f"(v.w) : "r"(a));
    return v;
}
__device__ __forceinline__ uint32_t cvt2(float lo, float hi) {
    uint32_t r;
    asm("cvt.rn.satfinite.bf16x2.f32 %0, %1, %2;" : "=r"(r) : "f"(hi), "f"(lo));
    return r;
}
__device__ __forceinline__ void ldmx4(uint32_t* r, uint32_t a) {
    asm volatile("ldmatrix.sync.aligned.m8n8.x4.shared.b16 {%0,%1,%2,%3}, [%4];"
                 : "=r"(r[0]), "=r"(r[1]), "=r"(r[2]), "=r"(r[3]) : "r"(a));
}
__device__ __forceinline__ void mma16816(float* c, const uint32_t* a, uint32_t b0, uint32_t b1) {
    asm volatile("mma.sync.aligned.m16n8k16.row.col.f32.bf16.bf16.f32 "
                 "{%0,%1,%2,%3}, {%4,%5,%6,%7}, {%8,%9}, {%0,%1,%2,%3};"
                 : "+f"(c[0]), "+f"(c[1]), "+f"(c[2]), "+f"(c[3])
                 : "r"(a[0]), "r"(a[1]), "r"(a[2]), "r"(a[3]), "r"(b0), "r"(b1));
}

// ---------------- CSR build over keys (dst*8 + rel) --------------------------
__global__ void k_count(const int* __restrict__ dst, const int* __restrict__ et) {
    int e = blockIdx.x * blockDim.x + threadIdx.x;
    if (e < EE) atomicAdd(&g_cnt[dst[e] * 8 + et[e]], 1);
}
__global__ void k_scan1() {
    int t = threadIdx.x, i = blockIdx.x * 1024 + t;
    int lane = t & 31, wid = t >> 5;
    int orig = (i < NK) ? g_cnt[i] : 0;
    int v = orig;
#pragma unroll
    for (int o = 1; o < 32; o <<= 1) {
        int nv = __shfl_up_sync(0xffffffffu, v, o);
        if (lane >= o) v += nv;
    }
    __shared__ int ws[32];
    if (lane == 31) ws[wid] = v;
    __syncthreads();
    if (wid == 0) {
        int wv = ws[lane];
#pragma unroll
        for (int o = 1; o < 32; o <<= 1) {
            int nv = __shfl_up_sync(0xffffffffu, wv, o);
            if (lane >= o) wv += nv;
        }
        ws[lane] = wv;
    }
    __syncthreads();
    int wpre = wid ? ws[wid - 1] : 0;
    if (i < NK) g_rowptr[i] = wpre + v - orig;
    if (t == 0) g_bsum[blockIdx.x] = ws[31];
}
__global__ void k_scan2() {
    int t = threadIdx.x;
    int lane = t & 31, wid = t >> 5;
    int orig = (t < NBLK2) ? g_bsum[t] : 0;
    int v = orig;
#pragma unroll
    for (int o = 1; o < 32; o <<= 1) {
        int nv = __shfl_up_sync(0xffffffffu, v, o);
        if (lane >= o) v += nv;
    }
    __shared__ int ws[32];
    if (lane == 31) ws[wid] = v;
    __syncthreads();
    if (wid == 0) {
        int wv = ws[lane];
#pragma unroll
        for (int o = 1; o < 32; o <<= 1) {
            int nv = __shfl_up_sync(0xffffffffu, wv, o);
            if (lane >= o) wv += nv;
        }
        ws[lane] = wv;
    }
    __syncthreads();
    int wpre = wid ? ws[wid - 1] : 0;
    if (t < NBLK2) g_bpre[t] = wpre + v - orig;
}
__global__ void k_scan3() {
    int i = blockIdx.x * 1024 + threadIdx.x;
    if (i < NK) {
        int v = g_rowptr[i] + g_bpre[blockIdx.x];
        g_rowptr[i] = v;
        g_cursor[i] = v;
    }
}
__global__ void k_build(const int* __restrict__ src, const int* __restrict__ dst,
                        const int* __restrict__ et) {
    int e = blockIdx.x * blockDim.x + threadIdx.x;
    if (e < EE) {
        int p = atomicAdd(&g_cursor[dst[e] * 8 + et[e]], 1);
        g_epack[p] = src[e];
    }
}

// ---------------- W precompute: transpose + bf16 hi/lo split ----------------
__global__ void k_prepw(const float* __restrict__ root, const float* __restrict__ W,
                        __nv_bfloat16* __restrict__ oh, __nv_bfloat16* __restrict__ ol,
                        int dout) {
    int i = blockIdx.x * 256 + threadIdx.x;
    if (i >= dout * KTOT) return;
    int n = i / KTOT, k = i % KTOT;
    float v = (k < 64) ? root[k * dout + n] : W[(size_t)(k - 64) * dout + n];
    __nv_bfloat16 h = __float2bfloat16(v);
    float lo = v - __bfloat162float(h);
    oh[i] = h;
    ol[i] = __float2bfloat16(lo);
}

// ---------------- fused coalesced-gather + mma.sync 3-pass GEMM -------------
template <int DOUT, bool RELU>
__global__ __launch_bounds__(256, 2) void k_gemm_fused(
    const float* __restrict__ X,
    const __nv_bfloat16* __restrict__ Wth, const __nv_bfloat16* __restrict__ Wtl,
    const float* __restrict__ bias, float* __restrict__ out) {
    constexpr int NT = DOUT / 8;            // n-tiles per warp
    constexpr int BP = 256 / DOUT;          // B copy: parts per row
    constexpr int BV = (64 * 2 / BP) / 16;  // uint4 per thread per B buffer
    constexpr int D = 8;                    // gather pipeline depth

    extern __shared__ __align__(16) char dyn[];
    uint32_t sAf = smem_u32(dyn);
    uint32_t sAh = sAf + 128 * AFS * 4;       // +34816
    uint32_t sAl = sAh + 128 * AS * 2;        // +18432
    uint32_t sBh = sAl + 128 * AS * 2;
    uint32_t sBl = sBh + DOUT * AS * 2;

    int tid = threadIdx.x;
    int w = tid >> 5, l = tid & 31;
    int m0 = blockIdx.x * 128;

    // B copy mapping
    int bn = tid % DOUT, bpart = tid / DOUT;
    uint4 bh4[BV], bl4[BV];
    auto loadB = [&](int c) {
        size_t off = (size_t)bn * KTOT + c * 64;
        const uint4* bh = reinterpret_cast<const uint4*>(Wth + off) + bpart * BV;
        const uint4* bl = reinterpret_cast<const uint4*>(Wtl + off) + bpart * BV;
#pragma unroll
        for (int v = 0; v < BV; v++) { bh4[v] = bh[v]; bl4[v] = bl[v]; }
    };
    auto storeB = [&]() {
        uint32_t bbase = (uint32_t)(bn * (AS * 2) + bpart * (BV * 16));
#pragma unroll
        for (int v = 0; v < BV; v++) {
            sts128(sBh + bbase + v * 16, bh4[v].x, bh4[v].y, bh4[v].z, bh4[v].w);
            sts128(sBl + bbase + v * 16, bl4[v].x, bl4[v].y, bl4[v].z, bl4[v].w);
        }
    };

    // convert-and-store: 8 float4 (one half-row, 32 floats) -> Ah/Al smem
    int crow = l & 15, cseg = l >> 4;       // convert-phase lane mapping
    int nrow = w * 16 + crow;
    uint32_t ab2 = (uint32_t)(nrow * (AS * 2) + cseg * 64);
    auto cvtstore = [&](float4* f) {
#pragma unroll
        for (int q = 0; q < 4; q++) {
            float4 p0 = f[2 * q], p1 = f[2 * q + 1];
            uint32_t h0 = cvt2(p0.x, p0.y), h1 = cvt2(p0.z, p0.w);
            uint32_t h2 = cvt2(p1.x, p1.y), h3 = cvt2(p1.z, p1.w);
            float r0 = p0.x - __uint_as_float(h0 << 16);
            float r1 = p0.y - __uint_as_float(h0 & 0xFFFF0000u);
            float r2 = p0.z - __uint_as_float(h1 << 16);
            float r3 = p0.w - __uint_as_float(h1 & 0xFFFF0000u);
            float r4 = p1.x - __uint_as_float(h2 << 16);
            float r5 = p1.y - __uint_as_float(h2 & 0xFFFF0000u);
            float r6 = p1.z - __uint_as_float(h3 << 16);
            float r7 = p1.w - __uint_as_float(h3 & 0xFFFF0000u);
            uint32_t l0 = cvt2(r0, r1), l1 = cvt2(r2, r3);
            uint32_t l2 = cvt2(r4, r5), l3 = cvt2(r6, r7);
            sts128(sAh + ab2 + q * 16, h0, h1, h2, h3);
            sts128(sAl + ab2 + q * 16, l0, l1, l2, l3);
        }
    };

    // zero own Af rows (warp-private; cols 0..63)
    {
        uint32_t afb = sAf + (uint32_t)((nrow * AFS + cseg * 32) * 4);
#pragma unroll
        for (int q = 0; q < 8; q++) sts128(afb + q * 16, 0u, 0u, 0u, 0u);
    }

    float acc[NT][4];
#pragma unroll
    for (int t = 0; t < NT; t++)
#pragma unroll
        for (int q = 0; q < 4; q++) acc[t][q] = 0.f;

    // ldmatrix / B-frag addresses
    int lrow = w * 16 + (l & 7) + ((l >> 3) & 1) * 8;
    uint32_t aoff = (uint32_t)(lrow * (AS * 2)) + ((l >> 4) & 1) * 16;
    int bfn = l >> 2;
    int bfk = (l & 3) * 4;

    loadB(0);
    for (int c = 0; c < NCH; c++) {
        storeB();
        // ---- gather A chunk c into Ah/Al (warp-private rows) ----
        if (c == 0) {
            int mg2 = m0 + nrow;
            float4 f[8];
            if (mg2 < NN) {
                const float4* xp = reinterpret_cast<const float4*>(X + (size_t)mg2 * 64 + cseg * 32);
#pragma unroll
                for (int q = 0; q < 8; q++) f[q] = xp[q];
            } else {
#pragma unroll
                for (int q = 0; q < 8; q++) f[q] = make_float4(0.f, 0.f, 0.f, 0.f);
            }
            cvtstore(f);
        } else {
            // per-node metadata in lanes 0..15
            int cn_l = 0, st_l = 0;
            if (l < 16) {
                int mg2 = m0 + w * 16 + l;
                if (mg2 < NN) {
                    int key = mg2 * 8 + (c - 1);
                    st_l = __ldg(g_rowptr + key);
                    cn_l = __ldg(g_cnt + key);
                }
            }
            int inc = cn_l;
#pragma unroll
            for (int o = 1; o < 32; o <<= 1) {
                int t2 = __shfl_up_sync(0xffffffffu, inc, o);
                if (l >= o) inc += t2;
            }
            int p_l = inc - cn_l;
            int T = __shfl_sync(0xffffffffu, inc, 15);

            if (T > 0) {
                float2 va[D]; uint32_t aa[D];
                auto loadbatch = [&](int jb, float2* v, uint32_t* ad) {
#pragma unroll
                    for (int d = 0; d < D; d++) {
                        int j = jb + d;
                        bool valid = j < T;
                        int jj = valid ? j : (T - 1);
                        unsigned mask = __ballot_sync(0xffffffffu, (l < 16) && (p_l <= jj));
                        int nd = 31 - __clz(mask);
                        int stn = __shfl_sync(0xffffffffu, st_l, nd);
                        int pn = __shfl_sync(0xffffffffu, p_l, nd);
                        int srci = __ldg(g_epack + stn + (jj - pn));
                        if (valid)
                            v[d] = *reinterpret_cast<const float2*>(X + (size_t)srci * 64 + l * 2);
                        ad[d] = valid
                            ? (sAf + (uint32_t)(((w * 16 + nd) * AFS + l * 2) * 4))
                            : 0u;
                    }
                };
                auto procbatch = [&](float2* v, uint32_t* ad) {
#pragma unroll
                    for (int d = 0; d < D; d++) {
                        if (ad[d]) {
                            float2 t2 = lds64f(ad[d]);
                            t2.x += v[d].x;
                            t2.y += v[d].y;
                            sts64f(ad[d], t2);
                        }
                    }
                };
                loadbatch(0, va, aa);
                for (int jb = 0; jb < T; jb += D) {
                    float2 vb[D]; uint32_t ab[D];
                    bool more = jb + D < T;
                    if (more) loadbatch(jb + D, vb, ab);
                    procbatch(va, aa);
                    if (more) {
#pragma unroll
                        for (int d = 0; d < D; d++) { va[d] = vb[d]; aa[d] = ab[d]; }
                    }
                }
            }
            // convert + re-zero Af
            int cnn = __shfl_sync(0xffffffffu, cn_l, crow);
            float invc = 1.0f / (float)max(cnn, 1);
            uint32_t afb = sAf + (uint32_t)((nrow * AFS + cseg * 32) * 4);
            float4 f[8];
#pragma unroll
            for (int q = 0; q < 8; q++) {
                float4 v = lds128f(afb + q * 16);
                sts128(afb + q * 16, 0u, 0u, 0u, 0u);
                v.x *= invc; v.y *= invc; v.z *= invc; v.w *= invc;
                f[q] = v;
            }
            cvtstore(f);
        }
        __syncthreads();
        if (c + 1 < NCH) loadB(c + 1);
        // ---- MMA for chunk c ----
#pragma unroll
        for (int ks = 0; ks < 4; ks++) {
            uint32_t fah[4], fal[4];
            ldmx4(fah, sAh + aoff + ks * 32);
            ldmx4(fal, sAl + aoff + ks * 32);
#pragma unroll
            for (int t = 0; t < NT; t++) {
                uint32_t ba = (uint32_t)((t * 8 + bfn) * (AS * 2)) + ks * 32 + bfk;
                uint32_t bh0 = lds32(sBh + ba), bh1 = lds32(sBh + ba + 16);
                uint32_t bl0 = lds32(sBl + ba), bl1 = lds32(sBl + ba + 16);
                mma16816(acc[t], fah, bh0, bh1);
                mma16816(acc[t], fah, bl0, bl1);
                mma16816(acc[t], fal, bh0, bh1);
            }
        }
        __syncthreads();
    }

    // epilogue
    int r0 = m0 + w * 16 + (l >> 2);
    int cb = (l & 3) * 2;
#pragma unroll
    for (int t = 0; t < NT; t++) {
        int n = t * 8 + cb;
        float b0 = __ldg(bias + n), b1 = __ldg(bias + n + 1);
        if (r0 < NN) {
            float v0 = acc[t][0] + b0, v1 = acc[t][1] + b1;
            if (RELU) { v0 = fmaxf(v0, 0.f); v1 = fmaxf(v1, 0.f); }
            *reinterpret_cast<float2*>(out + (size_t)r0 * DOUT + n) = make_float2(v0, v1);
        }
        if (r0 + 8 < NN) {
            float v2 = acc[t][2] + b0, v3 = acc[t][3] + b1;
            if (RELU) { v2 = fmaxf(v2, 0.f); v3 = fmaxf(v3, 0.f); }
            *reinterpret_cast<float2*>(out + (size_t)(r0 + 8) * DOUT + n) = make_float2(v2, v3);
        }
    }
}

// ---------------- launch ----------------------------------------------------
extern "C" void kernel_launch(void* const* d_in, const int* in_sizes, int n_in,
                              void* d_out, int out_size) {
    const float* x     = (const float*)d_in[0];
    const float* W1    = (const float*)d_in[1];
    const float* root1 = (const float*)d_in[2];
    const float* b1    = (const float*)d_in[3];
    const float* W2    = (const float*)d_in[4];
    const float* root2 = (const float*)d_in[5];
    const float* b2    = (const float*)d_in[6];
    const int*   src   = (const int*)d_in[7];
    const int*   dst   = (const int*)d_in[8];
    const int*   et    = (const int*)d_in[9];
    float* out = (float*)d_out;

    float* H;
    int* cntp;
    __nv_bfloat16 *w1h, *w1l, *w2h, *w2l;
    cudaGetSymbolAddress((void**)&H, g_H);
    cudaGetSymbolAddress((void**)&cntp, g_cnt);
    cudaGetSymbolAddress((void**)&w1h, g_Wt1h);
    cudaGetSymbolAddress((void**)&w1l, g_Wt1l);
    cudaGetSymbolAddress((void**)&w2h, g_Wt2h);
    cudaGetSymbolAddress((void**)&w2l, g_Wt2l);

    const int egrid = (EE + 255) / 256;
    const int ggrid = (NN + 127) / 128;
    const int smAF = 128 * AFS * 4;
    const int smA = 128 * AS * 2;
    const int smem64 = smAF + 2 * smA + 2 * 64 * AS * 2;
    const int smem32 = smAF + 2 * smA + 2 * 32 * AS * 2;

    static bool attr_done = false;
    if (!attr_done) {
        cudaFuncSetAttribute(k_gemm_fused<64, true>,
                             cudaFuncAttributeMaxDynamicSharedMemorySize, smem64);
        cudaFuncSetAttribute(k_gemm_fused<32, false>,
                             cudaFuncAttributeMaxDynamicSharedMemorySize, smem32);
        attr_done = true;
    }

    // CSR build over (dst, rel) keys
    cudaMemsetAsync(cntp, 0, NK * sizeof(int));
    k_count<<<egrid, 256>>>(dst, et);
    k_scan1<<<NBLK2, 1024>>>();
    k_scan2<<<1, 1024>>>();
    k_scan3<<<NBLK2, 1024>>>();
    k_build<<<egrid, 256>>>(src, dst, et);

    // weight prep
    k_prepw<<<(64 * KTOT + 255) / 256, 256>>>(root1, W1, w1h, w1l, 64);
    k_prepw<<<(32 * KTOT + 255) / 256, 256>>>(root2, W2, w2h, w2l, 32);

    // Layer 1 (fused aggregate+GEMM)
    k_gemm_fused<64, true><<<ggrid, 256, smem64>>>(x, w1h, w1l, b1, H);

    // Layer 2
    k_gemm_fused<32, false><<<ggrid, 256, smem32>>>(H, w2h, w2l, b2, out);
}

// round 7
// speedup vs baseline: 1.0577x; 1.0577x over previous
#include <cuda_runtime.h>
#include <cuda_bf16.h>
#include <cstdint>

typedef unsigned long long ull;

// Problem constants
constexpr int NN = 100000;
constexpr int EE = 1250000;
constexpr int KTOT = 576;                 // 64 (root) + 8*64
constexpr int NK = NN * 8;                // (rel, node) keys
constexpr int NBLK2 = (NK + 1023) / 1024; // 782 scan blocks
constexpr int NCH = 9;                    // 1 root chunk + 8 relation chunks
constexpr int AS = 72;                    // bf16 A/B smem row stride (144 B)
constexpr int AFS = 68;                   // fp32 accumulation tile row stride

// ---------------- scratch ---------------------------------------------------
__device__ int g_cnt[NK];
__device__ int g_rowptr[NK + 1];          // +1 sentinel (= EE)
__device__ int g_cursor[NK];
__device__ int g_epack[EE];               // src | (dst&15)<<20, sorted by (rel, dst)
__device__ int g_bsum[NBLK2];
__device__ int g_bpre[NBLK2];
__device__ float g_H[(size_t)NN * 64];
__device__ __nv_bfloat16 g_Wt1h[64 * KTOT];
__device__ __nv_bfloat16 g_Wt1l[64 * KTOT];
__device__ __nv_bfloat16 g_Wt2h[32 * KTOT];
__device__ __nv_bfloat16 g_Wt2l[32 * KTOT];

// ---------------- helpers ---------------------------------------------------
__device__ __forceinline__ uint32_t smem_u32(const void* p) {
    uint32_t a;
    asm("{ .reg .u64 t; cvta.to.shared.u64 t, %1; cvt.u32.u64 %0, t; }" : "=r"(a) : "l"(p));
    return a;
}
__device__ __forceinline__ void sts128(uint32_t a, uint32_t x, uint32_t y, uint32_t z, uint32_t w) {
    asm volatile("st.shared.v4.b32 [%0], {%1,%2,%3,%4};" :: "r"(a), "r"(x), "r"(y), "r"(z), "r"(w) : "memory");
}
__device__ __forceinline__ uint32_t lds32(uint32_t a) {
    uint32_t v;
    asm volatile("ld.shared.b32 %0, [%1];" : "=r"(v) : "r"(a));
    return v;
}
__device__ __forceinline__ void sts64f(uint32_t a, float2 v) {
    asm volatile("st.shared.v2.f32 [%0], {%1,%2};" :: "r"(a), "f"(v.x), "f"(v.y) : "memory");
}
__device__ __forceinline__ float4 lds128f(uint32_t a) {
    float4 v;
    asm volatile("ld.shared.v4.f32 {%0,%1,%2,%3}, [%4];"
                 : "=f"(v.x), "=f"(v.y), "=f"(v.z), "=f"(v.w) : "r"(a));
    return v;
}
__device__ __forceinline__ uint32_t cvt2(float lo, float hi) {
    uint32_t r;
    asm("cvt.rn.satfinite.bf16x2.f32 %0, %1, %2;" : "=r"(r) : "f"(hi), "f"(lo));
    return r;
}
__device__ __forceinline__ void ldmx4(uint32_t* r, uint32_t a) {
    asm volatile("ldmatrix.sync.aligned.m8n8.x4.shared.b16 {%0,%1,%2,%3}, [%4];"
                 : "=r"(r[0]), "=r"(r[1]), "=r"(r[2]), "=r"(r[3]) : "r"(a));
}
__device__ __forceinline__ void mma16816(float* c, const uint32_t* a, uint32_t b0, uint32_t b1) {
    asm volatile("mma.sync.aligned.m16n8k16.row.col.f32.bf16.bf16.f32 "
                 "{%0,%1,%2,%3}, {%4,%5,%6,%7}, {%8,%9}, {%0,%1,%2,%3};"
                 : "+f"(c[0]), "+f"(c[1]), "+f"(c[2]), "+f"(c[3])
                 : "r"(a[0]), "r"(a[1]), "r"(a[2]), "r"(a[3]), "r"(b0), "r"(b1));
}

// ---------------- CSR build over keys (rel*NN + dst) -------------------------
__global__ void k_count(const int* __restrict__ dst, const int* __restrict__ et) {
    int e = blockIdx.x * blockDim.x + threadIdx.x;
    if (e < EE) atomicAdd(&g_cnt[et[e] * NN + dst[e]], 1);
}
__global__ void k_scan1() {
    int t = threadIdx.x, i = blockIdx.x * 1024 + t;
    int lane = t & 31, wid = t >> 5;
    int orig = (i < NK) ? g_cnt[i] : 0;
    int v = orig;
#pragma unroll
    for (int o = 1; o < 32; o <<= 1) {
        int nv = __shfl_up_sync(0xffffffffu, v, o);
        if (lane >= o) v += nv;
    }
    __shared__ int ws[32];
    if (lane == 31) ws[wid] = v;
    __syncthreads();
    if (wid == 0) {
        int wv = ws[lane];
#pragma unroll
        for (int o = 1; o < 32; o <<= 1) {
            int nv = __shfl_up_sync(0xffffffffu, wv, o);
            if (lane >= o) wv += nv;
        }
        ws[lane] = wv;
    }
    __syncthreads();
    int wpre = wid ? ws[wid - 1] : 0;
    if (i < NK) g_rowptr[i] = wpre + v - orig;
    if (t == 0) g_bsum[blockIdx.x] = ws[31];
}
__global__ void k_scan2() {
    int t = threadIdx.x;
    int lane = t & 31, wid = t >> 5;
    int orig = (t < NBLK2) ? g_bsum[t] : 0;
    int v = orig;
#pragma unroll
    for (int o = 1; o < 32; o <<= 1) {
        int nv = __shfl_up_sync(0xffffffffu, v, o);
        if (lane >= o) v += nv;
    }
    __shared__ int ws[32];
    if (lane == 31) ws[wid] = v;
    __syncthreads();
    if (wid == 0) {
        int wv = ws[lane];
#pragma unroll
        for (int o = 1; o < 32; o <<= 1) {
            int nv = __shfl_up_sync(0xffffffffu, wv, o);
            if (lane >= o) wv += nv;
        }
        ws[lane] = wv;
    }
    __syncthreads();
    int wpre = wid ? ws[wid - 1] : 0;
    if (t < NBLK2) g_bpre[t] = wpre + v - orig;
}
__global__ void k_scan3() {
    int i = blockIdx.x * 1024 + threadIdx.x;
    if (i < NK) {
        int v = g_rowptr[i] + g_bpre[blockIdx.x];
        g_rowptr[i] = v;
        g_cursor[i] = v;
    }
    if (i == 0) g_rowptr[NK] = EE;  // sentinel for rel 7 end bound
}
__global__ void k_build(const int* __restrict__ src, const int* __restrict__ dst,
                        const int* __restrict__ et) {
    int e = blockIdx.x * blockDim.x + threadIdx.x;
    if (e < EE) {
        int d = dst[e];
        int p = atomicAdd(&g_cursor[et[e] * NN + d], 1);
        g_epack[p] = src[e] | ((d & 15) << 20);
    }
}

// ---------------- W precompute: transpose + bf16 hi/lo split ----------------
__global__ void k_prepw(const float* __restrict__ root, const float* __restrict__ W,
                        __nv_bfloat16* __restrict__ oh, __nv_bfloat16* __restrict__ ol,
                        int dout) {
    int i = blockIdx.x * 256 + threadIdx.x;
    if (i >= dout * KTOT) return;
    int n = i / KTOT, k = i % KTOT;
    float v = (k < 64) ? root[k * dout + n] : W[(size_t)(k - 64) * dout + n];
    __nv_bfloat16 h = __float2bfloat16(v);
    float lo = v - __bfloat162float(h);
    oh[i] = h;
    ol[i] = __float2bfloat16(lo);
}

// ---------------- fused coalesced-gather + mma.sync 3-pass GEMM -------------
// Edges sorted by (rel, dst): a warp's 16 nodes form one contiguous edge
// stream per relation; node slot = dst & 15 (packed in the record).
// Register accumulation with write-only flush on node change.
template <int DOUT, bool RELU>
__global__ __launch_bounds__(256, 2) void k_gemm_fused(
    const float* __restrict__ X,
    const __nv_bfloat16* __restrict__ Wth, const __nv_bfloat16* __restrict__ Wtl,
    const float* __restrict__ bias, float* __restrict__ out) {
    constexpr int NT = DOUT / 8;            // n-tiles per warp
    constexpr int BP = 256 / DOUT;          // B copy: parts per row
    constexpr int BV = (64 * 2 / BP) / 16;  // uint4 per thread per B buffer
    constexpr int D = 8;                    // gather pipeline depth

    extern __shared__ __align__(16) char dyn[];
    uint32_t sAf = smem_u32(dyn);
    uint32_t sAh = sAf + 128 * AFS * 4;
    uint32_t sAl = sAh + 128 * AS * 2;
    uint32_t sBh = sAl + 128 * AS * 2;
    uint32_t sBl = sBh + DOUT * AS * 2;

    int tid = threadIdx.x;
    int w = tid >> 5, l = tid & 31;
    int m0 = blockIdx.x * 128;

    // B copy mapping
    int bn = tid % DOUT, bpart = tid / DOUT;
    uint4 bh4[BV], bl4[BV];
    auto loadB = [&](int c) {
        size_t off = (size_t)bn * KTOT + c * 64;
        const uint4* bh = reinterpret_cast<const uint4*>(Wth + off) + bpart * BV;
        const uint4* bl = reinterpret_cast<const uint4*>(Wtl + off) + bpart * BV;
#pragma unroll
        for (int v = 0; v < BV; v++) { bh4[v] = bh[v]; bl4[v] = bl[v]; }
    };
    auto storeB = [&]() {
        uint32_t bbase = (uint32_t)(bn * (AS * 2) + bpart * (BV * 16));
#pragma unroll
        for (int v = 0; v < BV; v++) {
            sts128(sBh + bbase + v * 16, bh4[v].x, bh4[v].y, bh4[v].z, bh4[v].w);
            sts128(sBl + bbase + v * 16, bl4[v].x, bl4[v].y, bl4[v].z, bl4[v].w);
        }
    };

    // convert-and-store mapping: 2 lanes per node row (32 floats each)
    int crow = l & 15, cseg = l >> 4;
    int nrow = w * 16 + crow;
    uint32_t ab2 = (uint32_t)(nrow * (AS * 2) + cseg * 64);
    auto cvtstore = [&](float4* f) {
#pragma unroll
        for (int q = 0; q < 4; q++) {
            float4 p0 = f[2 * q], p1 = f[2 * q + 1];
            uint32_t h0 = cvt2(p0.x, p0.y), h1 = cvt2(p0.z, p0.w);
            uint32_t h2 = cvt2(p1.x, p1.y), h3 = cvt2(p1.z, p1.w);
            float r0 = p0.x - __uint_as_float(h0 << 16);
            float r1 = p0.y - __uint_as_float(h0 & 0xFFFF0000u);
            float r2 = p0.z - __uint_as_float(h1 << 16);
            float r3 = p0.w - __uint_as_float(h1 & 0xFFFF0000u);
            float r4 = p1.x - __uint_as_float(h2 << 16);
            float r5 = p1.y - __uint_as_float(h2 & 0xFFFF0000u);
            float r6 = p1.z - __uint_as_float(h3 << 16);
            float r7 = p1.w - __uint_as_float(h3 & 0xFFFF0000u);
            uint32_t l0 = cvt2(r0, r1), l1 = cvt2(r2, r3);
            uint32_t l2 = cvt2(r4, r5), l3 = cvt2(r6, r7);
            sts128(sAh + ab2 + q * 16, h0, h1, h2, h3);
            sts128(sAl + ab2 + q * 16, l0, l1, l2, l3);
        }
    };

    // zero own Af rows (warp-private)
    {
        uint32_t afb = sAf + (uint32_t)((nrow * AFS + cseg * 32) * 4);
#pragma unroll
        for (int q = 0; q < 8; q++) sts128(afb + q * 16, 0u, 0u, 0u, 0u);
    }

    float acc[NT][4];
#pragma unroll
    for (int t = 0; t < NT; t++)
#pragma unroll
        for (int q = 0; q < 4; q++) acc[t][q] = 0.f;

    // ldmatrix / B-frag addresses
    int lrow = w * 16 + (l & 7) + ((l >> 3) & 1) * 8;
    uint32_t aoff = (uint32_t)(lrow * (AS * 2)) + ((l >> 4) & 1) * 16;
    int bfn = l >> 2;
    int bfk = (l & 3) * 4;

    loadB(0);
    for (int c = 0; c < NCH; c++) {
        storeB();
        // ---- build A chunk c (warp-private rows) ----
        if (c == 0) {
            int mg2 = m0 + nrow;
            float4 f[8];
            if (mg2 < NN) {
                const float4* xp = reinterpret_cast<const float4*>(X + (size_t)mg2 * 64 + cseg * 32);
#pragma unroll
                for (int q = 0; q < 8; q++) f[q] = xp[q];
            } else {
#pragma unroll
                for (int q = 0; q < 8; q++) f[q] = make_float4(0.f, 0.f, 0.f, 0.f);
            }
            cvtstore(f);
        } else {
            int r = c - 1;
            int nb = m0 + w * 16;
            int st = __ldg(g_rowptr + r * NN + min(nb, NN));
            int en = __ldg(g_rowptr + r * NN + min(nb + 16, NN));
            int T = en - st;

            if (T > 0) {
                // contiguous edge stream; node slot in record bits [20:24)
                float2 sum = make_float2(0.f, 0.f);
                int cur = -1;
                int rec0[D], rec1[D];
                float2 val[D];
                auto ldrecs = [&](int jb, int* rc) {
#pragma unroll
                    for (int d = 0; d < D; d++) {
                        int j = jb + d;
                        rc[d] = (j < T) ? __ldg(g_epack + st + j) : -1;
                    }
                };
                auto ldvals = [&](const int* rc, float2* v) {
#pragma unroll
                    for (int d = 0; d < D; d++) {
                        if (rc[d] >= 0) {
                            int srci = rc[d] & 0xFFFFF;
                            v[d] = *reinterpret_cast<const float2*>(X + (size_t)srci * 64 + l * 2);
                        }
                    }
                };
                ldrecs(0, rec0);
                ldrecs(D, rec1);
                ldvals(rec0, val);
                for (int jb = 0; jb < T; jb += D) {
                    float2 vn[D];
                    ldvals(rec1, vn);
#pragma unroll
                    for (int d = 0; d < D; d++) {
                        int rc = rec0[d];
                        if (rc >= 0) {  // warp-uniform
                            int nd = (rc >> 20) & 15;
                            if (nd != cur) {
                                if (cur >= 0)
                                    sts64f(sAf + (uint32_t)(((w * 16 + cur) * AFS + l * 2) * 4), sum);
                                sum = make_float2(0.f, 0.f);
                                cur = nd;
                            }
                            sum.x += val[d].x;
                            sum.y += val[d].y;
                        }
                    }
#pragma unroll
                    for (int d = 0; d < D; d++) { rec0[d] = rec1[d]; val[d] = vn[d]; }
                    ldrecs(jb + 2 * D, rec1);
                }
                if (cur >= 0)
                    sts64f(sAf + (uint32_t)(((w * 16 + cur) * AFS + l * 2) * 4), sum);
            }
            __syncwarp();
            // normalize + convert + re-zero Af
            int mg2 = m0 + nrow;
            int cnn = (mg2 < NN) ? __ldg(g_cnt + r * NN + mg2) : 0;
            float invc = 1.0f / (float)max(cnn, 1);
            uint32_t afb = sAf + (uint32_t)((nrow * AFS + cseg * 32) * 4);
            float4 f[8];
#pragma unroll
            for (int q = 0; q < 8; q++) {
                float4 v = lds128f(afb + q * 16);
                sts128(afb + q * 16, 0u, 0u, 0u, 0u);
                v.x *= invc; v.y *= invc; v.z *= invc; v.w *= invc;
                f[q] = v;
            }
            cvtstore(f);
        }
        __syncthreads();
        if (c + 1 < NCH) loadB(c + 1);
        // ---- MMA for chunk c ----
#pragma unroll
        for (int ks = 0; ks < 4; ks++) {
            uint32_t fah[4], fal[4];
            ldmx4(fah, sAh + aoff + ks * 32);
            ldmx4(fal, sAl + aoff + ks * 32);
#pragma unroll
            for (int t = 0; t < NT; t++) {
                uint32_t ba = (uint32_t)((t * 8 + bfn) * (AS * 2)) + ks * 32 + bfk;
                uint32_t bh0 = lds32(sBh + ba), bh1 = lds32(sBh + ba + 16);
                uint32_t bl0 = lds32(sBl + ba), bl1 = lds32(sBl + ba + 16);
                mma16816(acc[t], fah, bh0, bh1);
                mma16816(acc[t], fah, bl0, bl1);
                mma16816(acc[t], fal, bh0, bh1);
            }
        }
        __syncthreads();
    }

    // epilogue
    int r0 = m0 + w * 16 + (l >> 2);
    int cb = (l & 3) * 2;
#pragma unroll
    for (int t = 0; t < NT; t++) {
        int n = t * 8 + cb;
        float b0 = __ldg(bias + n), b1 = __ldg(bias + n + 1);
        if (r0 < NN) {
            float v0 = acc[t][0] + b0, v1 = acc[t][1] + b1;
            if (RELU) { v0 = fmaxf(v0, 0.f); v1 = fmaxf(v1, 0.f); }
            *reinterpret_cast<float2*>(out + (size_t)r0 * DOUT + n) = make_float2(v0, v1);
        }
        if (r0 + 8 < NN) {
            float v2 = acc[t][2] + b0, v3 = acc[t][3] + b1;
            if (RELU) { v2 = fmaxf(v2, 0.f); v3 = fmaxf(v3, 0.f); }
            *reinterpret_cast<float2*>(out + (size_t)(r0 + 8) * DOUT + n) = make_float2(v2, v3);
        }
    }
}

// ---------------- launch ----------------------------------------------------
extern "C" void kernel_launch(void* const* d_in, const int* in_sizes, int n_in,
                              void* d_out, int out_size) {
    const float* x     = (const float*)d_in[0];
    const float* W1    = (const float*)d_in[1];
    const float* root1 = (const float*)d_in[2];
    const float* b1    = (const float*)d_in[3];
    const float* W2    = (const float*)d_in[4];
    const float* root2 = (const float*)d_in[5];
    const float* b2    = (const float*)d_in[6];
    const int*   src   = (const int*)d_in[7];
    const int*   dst   = (const int*)d_in[8];
    const int*   et    = (const int*)d_in[9];
    float* out = (float*)d_out;

    float* H;
    int* cntp;
    __nv_bfloat16 *w1h, *w1l, *w2h, *w2l;
    cudaGetSymbolAddress((void**)&H, g_H);
    cudaGetSymbolAddress((void**)&cntp, g_cnt);
    cudaGetSymbolAddress((void**)&w1h, g_Wt1h);
    cudaGetSymbolAddress((void**)&w1l, g_Wt1l);
    cudaGetSymbolAddress((void**)&w2h, g_Wt2h);
    cudaGetSymbolAddress((void**)&w2l, g_Wt2l);

    const int egrid = (EE + 255) / 256;
    const int ggrid = (NN + 127) / 128;
    const int smAF = 128 * AFS * 4;
    const int smA = 128 * AS * 2;
    const int smem64 = smAF + 2 * smA + 2 * 64 * AS * 2;
    const int smem32 = smAF + 2 * smA + 2 * 32 * AS * 2;

    static bool attr_done = false;
    if (!attr_done) {
        cudaFuncSetAttribute(k_gemm_fused<64, true>,
                             cudaFuncAttributeMaxDynamicSharedMemorySize, smem64);
        cudaFuncSetAttribute(k_gemm_fused<32, false>,
                             cudaFuncAttributeMaxDynamicSharedMemorySize, smem32);
        attr_done = true;
    }

    // CSR build over (rel, dst) keys
    cudaMemsetAsync(cntp, 0, NK * sizeof(int));
    k_count<<<egrid, 256>>>(dst, et);
    k_scan1<<<NBLK2, 1024>>>();
    k_scan2<<<1, 1024>>>();
    k_scan3<<<NBLK2, 1024>>>();
    k_build<<<egrid, 256>>>(src, dst, et);

    // weight prep
    k_prepw<<<(64 * KTOT + 255) / 256, 256>>>(root1, W1, w1h, w1l, 64);
    k_prepw<<<(32 * KTOT + 255) / 256, 256>>>(root2, W2, w2h, w2l, 32);

    // Layer 1 (fused aggregate+GEMM)
    k_gemm_fused<64, true><<<ggrid, 256, smem64>>>(x, w1h, w1l, b1, H);

    // Layer 2
    k_gemm_fused<32, false><<<ggrid, 256, smem32>>>(H, w2h, w2l, b2, out);
}

// round 8
// speedup vs baseline: 1.3877x; 1.3119x over previous
#include <cuda_runtime.h>
#include <cuda_bf16.h>
#include <cstdint>

typedef unsigned long long ull;

// Problem constants
constexpr int NN = 100000;
constexpr int EE = 1250000;
constexpr int KTOT = 576;                 // 64 (root) + 8*64
constexpr int NK = NN * 8;                // (dst, rel) keys
constexpr int NBLK2 = (NK + 1023) / 1024; // 782 scan blocks
constexpr int NCH = 9;                    // 1 root chunk + 8 relation chunks
constexpr int AS = 72;                    // bf16 A/B smem row stride (144 B)

// ---------------- scratch ---------------------------------------------------
__device__ int g_cnt[NK];
__device__ int g_rowptr[NK + 1];          // +1 sentinel (= EE)
__device__ int g_cursor[NK];
__device__ int g_epack[EE];               // src ids sorted by (dst, rel)
__device__ int g_bsum[NBLK2];
__device__ int g_bpre[NBLK2];
__device__ float g_H[(size_t)NN * 64];
__device__ __nv_bfloat16 g_Wt1h[64 * KTOT];
__device__ __nv_bfloat16 g_Wt1l[64 * KTOT];
__device__ __nv_bfloat16 g_Wt2h[32 * KTOT];
__device__ __nv_bfloat16 g_Wt2l[32 * KTOT];

// ---------------- helpers ---------------------------------------------------
__device__ __forceinline__ uint32_t smem_u32(const void* p) {
    uint32_t a;
    asm("{ .reg .u64 t; cvta.to.shared.u64 t, %1; cvt.u32.u64 %0, t; }" : "=r"(a) : "l"(p));
    return a;
}
__device__ __forceinline__ void sts128(uint32_t a, uint32_t x, uint32_t y, uint32_t z, uint32_t w) {
    asm volatile("st.shared.v4.b32 [%0], {%1,%2,%3,%4};" :: "r"(a), "r"(x), "r"(y), "r"(z), "r"(w) : "memory");
}
__device__ __forceinline__ void sts64(uint32_t a, uint32_t x, uint32_t y) {
    asm volatile("st.shared.v2.b32 [%0], {%1,%2};" :: "r"(a), "r"(x), "r"(y) : "memory");
}
__device__ __forceinline__ uint32_t lds32(uint32_t a) {
    uint32_t v;
    asm volatile("ld.shared.b32 %0, [%1];" : "=r"(v) : "r"(a));
    return v;
}
__device__ __forceinline__ uint32_t cvt2(float lo, float hi) {
    uint32_t r;
    asm("cvt.rn.satfinite.bf16x2.f32 %0, %1, %2;" : "=r"(r) : "f"(hi), "f"(lo));
    return r;
}
__device__ __forceinline__ void ldmx4(uint32_t* r, uint32_t a) {
    asm volatile("ldmatrix.sync.aligned.m8n8.x4.shared.b16 {%0,%1,%2,%3}, [%4];"
                 : "=r"(r[0]), "=r"(r[1]), "=r"(r[2]), "=r"(r[3]) : "r"(a));
}
__device__ __forceinline__ void mma16816(float* c, const uint32_t* a, uint32_t b0, uint32_t b1) {
    asm volatile("mma.sync.aligned.m16n8k16.row.col.f32.bf16.bf16.f32 "
                 "{%0,%1,%2,%3}, {%4,%5,%6,%7}, {%8,%9}, {%0,%1,%2,%3};"
                 : "+f"(c[0]), "+f"(c[1]), "+f"(c[2]), "+f"(c[3])
                 : "r"(a[0]), "r"(a[1]), "r"(a[2]), "r"(a[3]), "r"(b0), "r"(b1));
}

// ---------------- CSR build over keys (dst*8 + rel) --------------------------
__global__ void k_count(const int* __restrict__ dst, const int* __restrict__ et) {
    int e = blockIdx.x * blockDim.x + threadIdx.x;
    if (e < EE) atomicAdd(&g_cnt[dst[e] * 8 + et[e]], 1);
}
__global__ void k_scan1() {
    int t = threadIdx.x, i = blockIdx.x * 1024 + t;
    int lane = t & 31, wid = t >> 5;
    int orig = (i < NK) ? g_cnt[i] : 0;
    int v = orig;
#pragma unroll
    for (int o = 1; o < 32; o <<= 1) {
        int nv = __shfl_up_sync(0xffffffffu, v, o);
        if (lane >= o) v += nv;
    }
    __shared__ int ws[32];
    if (lane == 31) ws[wid] = v;
    __syncthreads();
    if (wid == 0) {
        int wv = ws[lane];
#pragma unroll
        for (int o = 1; o < 32; o <<= 1) {
            int nv = __shfl_up_sync(0xffffffffu, wv, o);
            if (lane >= o) wv += nv;
        }
        ws[lane] = wv;
    }
    __syncthreads();
    int wpre = wid ? ws[wid - 1] : 0;
    if (i < NK) g_rowptr[i] = wpre + v - orig;
    if (t == 0) g_bsum[blockIdx.x] = ws[31];
}
__global__ void k_scan2() {
    int t = threadIdx.x;
    int lane = t & 31, wid = t >> 5;
    int orig = (t < NBLK2) ? g_bsum[t] : 0;
    int v = orig;
#pragma unroll
    for (int o = 1; o < 32; o <<= 1) {
        int nv = __shfl_up_sync(0xffffffffu, v, o);
        if (lane >= o) v += nv;
    }
    __shared__ int ws[32];
    if (lane == 31) ws[wid] = v;
    __syncthreads();
    if (wid == 0) {
        int wv = ws[lane];
#pragma unroll
        for (int o = 1; o < 32; o <<= 1) {
            int nv = __shfl_up_sync(0xffffffffu, wv, o);
            if (lane >= o) wv += nv;
        }
        ws[lane] = wv;
    }
    __syncthreads();
    int wpre = wid ? ws[wid - 1] : 0;
    if (t < NBLK2) g_bpre[t] = wpre + v - orig;
}
__global__ void k_scan3() {
    int i = blockIdx.x * 1024 + threadIdx.x;
    if (i < NK) {
        int v = g_rowptr[i] + g_bpre[blockIdx.x];
        g_rowptr[i] = v;
        g_cursor[i] = v;
    }
    if (i == 0) g_rowptr[NK] = EE;  // sentinel
}
__global__ void k_build(const int* __restrict__ src, const int* __restrict__ dst,
                        const int* __restrict__ et) {
    int e = blockIdx.x * blockDim.x + threadIdx.x;
    if (e < EE) {
        int p = atomicAdd(&g_cursor[dst[e] * 8 + et[e]], 1);
        g_epack[p] = src[e];
    }
}

// ---------------- W precompute: transpose + bf16 hi/lo split ----------------
__global__ void k_prepw(const float* __restrict__ root, const float* __restrict__ W,
                        __nv_bfloat16* __restrict__ oh, __nv_bfloat16* __restrict__ ol,
                        int dout) {
    int i = blockIdx.x * 256 + threadIdx.x;
    if (i >= dout * KTOT) return;
    int n = i / KTOT, k = i % KTOT;
    float v = (k < 64) ? root[k * dout + n] : W[(size_t)(k - 64) * dout + n];
    __nv_bfloat16 h = __float2bfloat16(v);
    float lo = v - __bfloat162float(h);
    oh[i] = h;
    ol[i] = __float2bfloat16(lo);
}

// ---------------- fused 8-lane/row gather + mma.sync 3-pass GEMM ------------
// Gather: warp = 4 node-groups x 8 lanes; lane owns 32 B of the 256 B row
// (float4 at jl*16 and 128+jl*16) -> 4 L1tex lines per warp-LDG (minimal),
// 4 independent edge streams per warp, register accumulation, no smem RMW.
template <int DOUT, bool RELU>
__global__ __launch_bounds__(256, 2) void k_gemm_fused(
    const float* __restrict__ X,
    const __nv_bfloat16* __restrict__ Wth, const __nv_bfloat16* __restrict__ Wtl,
    const float* __restrict__ bias, float* __restrict__ out) {
    constexpr int NT = DOUT / 8;            // n-tiles per warp
    constexpr int BP = 256 / DOUT;          // B copy: parts per row
    constexpr int BV = (64 * 2 / BP) / 16;  // uint4 per thread per B buffer

    extern __shared__ __align__(16) char dyn[];
    uint32_t sAh = smem_u32(dyn);
    uint32_t sAl = sAh + 128 * AS * 2;
    uint32_t sBh = sAl + 128 * AS * 2;
    uint32_t sBl = sBh + DOUT * AS * 2;

    int tid = threadIdx.x;
    int w = tid >> 5, l = tid & 31;
    int m0 = blockIdx.x * 128;

    int jl = l & 7;   // col part (32 B of the row)
    int ns = l >> 3;  // node sub-index within warp group of 4

    // B copy mapping
    int bn = tid % DOUT, bpart = tid / DOUT;
    uint4 bh4[BV], bl4[BV];
    auto loadB = [&](int c) {
        size_t off = (size_t)bn * KTOT + c * 64;
        const uint4* bh = reinterpret_cast<const uint4*>(Wth + off) + bpart * BV;
        const uint4* bl = reinterpret_cast<const uint4*>(Wtl + off) + bpart * BV;
#pragma unroll
        for (int v = 0; v < BV; v++) { bh4[v] = bh[v]; bl4[v] = bl[v]; }
    };
    auto storeB = [&]() {
        uint32_t bbase = (uint32_t)(bn * (AS * 2) + bpart * (BV * 16));
#pragma unroll
        for (int v = 0; v < BV; v++) {
            sts128(sBh + bbase + v * 16, bh4[v].x, bh4[v].y, bh4[v].z, bh4[v].w);
            sts128(sBl + bbase + v * 16, bl4[v].x, bl4[v].y, bl4[v].z, bl4[v].w);
        }
    };

    // convert 8 floats (2 float4) of row nrow, col part jl -> Ah/Al
    auto cvst = [&](int nrow, float4 v0, float4 v1, float inv) {
        v0.x *= inv; v0.y *= inv; v0.z *= inv; v0.w *= inv;
        v1.x *= inv; v1.y *= inv; v1.z *= inv; v1.w *= inv;
        uint32_t h0 = cvt2(v0.x, v0.y), h1 = cvt2(v0.z, v0.w);
        uint32_t h2 = cvt2(v1.x, v1.y), h3 = cvt2(v1.z, v1.w);
        float r0 = v0.x - __uint_as_float(h0 << 16);
        float r1 = v0.y - __uint_as_float(h0 & 0xFFFF0000u);
        float r2 = v0.z - __uint_as_float(h1 << 16);
        float r3 = v0.w - __uint_as_float(h1 & 0xFFFF0000u);
        float r4 = v1.x - __uint_as_float(h2 << 16);
        float r5 = v1.y - __uint_as_float(h2 & 0xFFFF0000u);
        float r6 = v1.z - __uint_as_float(h3 << 16);
        float r7 = v1.w - __uint_as_float(h3 & 0xFFFF0000u);
        uint32_t l0 = cvt2(r0, r1), l1 = cvt2(r2, r3);
        uint32_t l2 = cvt2(r4, r5), l3 = cvt2(r6, r7);
        uint32_t base = (uint32_t)(nrow * (AS * 2)) + jl * 8;
        sts64(sAh + base, h0, h1);
        sts64(sAh + base + 64, h2, h3);
        sts64(sAl + base, l0, l1);
        sts64(sAl + base + 64, l2, l3);
    };

    float acc[NT][4];
#pragma unroll
    for (int t = 0; t < NT; t++)
#pragma unroll
        for (int q = 0; q < 4; q++) acc[t][q] = 0.f;

    // ldmatrix / B-frag addresses
    int lrow = w * 16 + (l & 7) + ((l >> 3) & 1) * 8;
    uint32_t aoff = (uint32_t)(lrow * (AS * 2)) + ((l >> 4) & 1) * 16;
    int bfn = l >> 2;
    int bfk = (l & 3) * 4;

    loadB(0);
    for (int c = 0; c < NCH; c++) {
        storeB();
        // ---- build A chunk c ----
        if (c == 0) {
#pragma unroll
            for (int p = 0; p < 4; p++) {
                int mg = m0 + w * 16 + p * 4 + ns;
                float4 v0 = make_float4(0.f, 0.f, 0.f, 0.f), v1 = v0;
                if (mg < NN) {
                    const float4* xp = reinterpret_cast<const float4*>(X + (size_t)mg * 64);
                    v0 = xp[jl];
                    v1 = xp[8 + jl];
                }
                cvst(w * 16 + p * 4 + ns, v0, v1, 1.0f);
            }
        } else {
            int r = c - 1;
            int st[4], cn[4];
#pragma unroll
            for (int p = 0; p < 4; p++) {
                int mg = m0 + w * 16 + p * 4 + ns;
                if (mg < NN) {
                    int key = mg * 8 + r;
                    int s0 = __ldg(g_rowptr + key);
                    st[p] = s0;
                    cn[p] = __ldg(g_rowptr + key + 1) - s0;
                } else {
                    st[p] = 0;
                    cn[p] = 0;
                }
            }
            int mx = max(max(cn[0], cn[1]), max(cn[2], cn[3]));
            float4 a0[4], a1[4];
#pragma unroll
            for (int p = 0; p < 4; p++) {
                a0[p] = make_float4(0.f, 0.f, 0.f, 0.f);
                a1[p] = make_float4(0.f, 0.f, 0.f, 0.f);
            }
            int rec[4];
#pragma unroll
            for (int p = 0; p < 4; p++)
                rec[p] = (cn[p] > 0) ? __ldg(g_epack + st[p]) : -1;
            for (int j = 0; j < mx; j++) {
                float4 v0[4], v1[4];
#pragma unroll
                for (int p = 0; p < 4; p++) {
                    if (rec[p] >= 0) {
                        const float4* xp = reinterpret_cast<const float4*>(X + (size_t)rec[p] * 64);
                        v0[p] = xp[jl];
                        v1[p] = xp[8 + jl];
                    }
                }
#pragma unroll
                for (int p = 0; p < 4; p++) {
                    bool more = (j + 1 < cn[p]);
                    int nr = more ? __ldg(g_epack + st[p] + j + 1) : -1;
                    if (rec[p] >= 0) {
                        a0[p].x += v0[p].x; a0[p].y += v0[p].y;
                        a0[p].z += v0[p].z; a0[p].w += v0[p].w;
                        a1[p].x += v1[p].x; a1[p].y += v1[p].y;
                        a1[p].z += v1[p].z; a1[p].w += v1[p].w;
                    }
                    rec[p] = nr;
                }
            }
#pragma unroll
            for (int p = 0; p < 4; p++) {
                float inv = 1.0f / (float)max(cn[p], 1);
                cvst(w * 16 + p * 4 + ns, a0[p], a1[p], inv);
            }
        }
        __syncthreads();
        if (c + 1 < NCH) loadB(c + 1);
        // ---- MMA for chunk c ----
#pragma unroll
        for (int ks = 0; ks < 4; ks++) {
            uint32_t fah[4], fal[4];
            ldmx4(fah, sAh + aoff + ks * 32);
            ldmx4(fal, sAl + aoff + ks * 32);
#pragma unroll
            for (int t = 0; t < NT; t++) {
                uint32_t ba = (uint32_t)((t * 8 + bfn) * (AS * 2)) + ks * 32 + bfk;
                uint32_t bh0 = lds32(sBh + ba), bh1 = lds32(sBh + ba + 16);
                uint32_t bl0 = lds32(sBl + ba), bl1 = lds32(sBl + ba + 16);
                mma16816(acc[t], fah, bh0, bh1);
                mma16816(acc[t], fah, bl0, bl1);
                mma16816(acc[t], fal, bh0, bh1);
            }
        }
        __syncthreads();
    }

    // epilogue
    int r0 = m0 + w * 16 + (l >> 2);
    int cb = (l & 3) * 2;
#pragma unroll
    for (int t = 0; t < NT; t++) {
        int n = t * 8 + cb;
        float b0 = __ldg(bias + n), b1 = __ldg(bias + n + 1);
        if (r0 < NN) {
            float v0 = acc[t][0] + b0, v1 = acc[t][1] + b1;
            if (RELU) { v0 = fmaxf(v0, 0.f); v1 = fmaxf(v1, 0.f); }
            *reinterpret_cast<float2*>(out + (size_t)r0 * DOUT + n) = make_float2(v0, v1);
        }
        if (r0 + 8 < NN) {
            float v2 = acc[t][2] + b0, v3 = acc[t][3] + b1;
            if (RELU) { v2 = fmaxf(v2, 0.f); v3 = fmaxf(v3, 0.f); }
            *reinterpret_cast<float2*>(out + (size_t)(r0 + 8) * DOUT + n) = make_float2(v2, v3);
        }
    }
}

// ---------------- launch ----------------------------------------------------
extern "C" void kernel_launch(void* const* d_in, const int* in_sizes, int n_in,
                              void* d_out, int out_size) {
    const float* x     = (const float*)d_in[0];
    const float* W1    = (const float*)d_in[1];
    const float* root1 = (const float*)d_in[2];
    const float* b1    = (const float*)d_in[3];
    const float* W2    = (const float*)d_in[4];
    const float* root2 = (const float*)d_in[5];
    const float* b2    = (const float*)d_in[6];
    const int*   src   = (const int*)d_in[7];
    const int*   dst   = (const int*)d_in[8];
    const int*   et    = (const int*)d_in[9];
    float* out = (float*)d_out;

    float* H;
    int* cntp;
    __nv_bfloat16 *w1h, *w1l, *w2h, *w2l;
    cudaGetSymbolAddress((void**)&H, g_H);
    cudaGetSymbolAddress((void**)&cntp, g_cnt);
    cudaGetSymbolAddress((void**)&w1h, g_Wt1h);
    cudaGetSymbolAddress((void**)&w1l, g_Wt1l);
    cudaGetSymbolAddress((void**)&w2h, g_Wt2h);
    cudaGetSymbolAddress((void**)&w2l, g_Wt2l);

    const int egrid = (EE + 255) / 256;
    const int ggrid = (NN + 127) / 128;
    const int smA = 128 * AS * 2;
    const int smem64 = 2 * smA + 2 * 64 * AS * 2;
    const int smem32 = 2 * smA + 2 * 32 * AS * 2;

    static bool attr_done = false;
    if (!attr_done) {
        cudaFuncSetAttribute(k_gemm_fused<64, true>,
                             cudaFuncAttributeMaxDynamicSharedMemorySize, smem64);
        cudaFuncSetAttribute(k_gemm_fused<32, false>,
                             cudaFuncAttributeMaxDynamicSharedMemorySize, smem32);
        attr_done = true;
    }

    // CSR build over (dst, rel) keys
    cudaMemsetAsync(cntp, 0, NK * sizeof(int));
    k_count<<<egrid, 256>>>(dst, et);
    k_scan1<<<NBLK2, 1024>>>();
    k_scan2<<<1, 1024>>>();
    k_scan3<<<NBLK2, 1024>>>();
    k_build<<<egrid, 256>>>(src, dst, et);

    // weight prep
    k_prepw<<<(64 * KTOT + 255) / 256, 256>>>(root1, W1, w1h, w1l, 64);
    k_prepw<<<(32 * KTOT + 255) / 256, 256>>>(root2, W2, w2h, w2l, 32);

    // Layer 1 (fused aggregate+GEMM)
    k_gemm_fused<64, true><<<ggrid, 256, smem64>>>(x, w1h, w1l, b1, H);

    // Layer 2
    k_gemm_fused<32, false><<<ggrid, 256, smem32>>>(H, w2h, w2l, b2, out);
}